// round 2
// baseline (speedup 1.0000x reference)
#include <cuda_runtime.h>

// GATv2 x3 layers. N=100000 nodes, E=1000000 edges, C=64, H=4, O=16.
//
// Pipeline per layer:
//   1. gemm_lr   : xl = in@Wl, xr = in@Wr            (smem-tiled fp32 FMA)
//   2. zero      : out accumulator + denom
//   3. edge_pass1: e = a . lrelu(xl[src]+xr[dst]); ex=exp(e); denom[dst] += ex
//      (segment-max skipped: alpha invariant to shift; logits are O(1))
//   4. edge_pass2: alpha = ex/denom[dst]; out[dst] += alpha * xl[src]  (atomics)
//   5. finalize  : +bias, relu (layers 1,2) -> g_h, or -> d_out (layer 3)

#define NN 100000
#define EE 1000000
#define CC 64
#define HH 4
#define OO 16
#define NEG_SLOPE 0.2f

// ---- scratch (device globals; no runtime allocation allowed) ----
__device__ float g_xl[NN * CC];        // 25.6 MB
__device__ float g_xr[NN * CC];        // 25.6 MB
__device__ float g_h[NN * CC];         // 25.6 MB  (layer output / next input)
__device__ float g_out[NN * CC];       // 25.6 MB  (atomic accumulator)
__device__ float g_ex[EE * HH];        // 16 MB    (exp(logit) per edge,head)
__device__ float g_denom[NN * HH];     // 1.6 MB
__device__ int   g_src[EE];            // 4 MB
__device__ int   g_dst[EE];            // 4 MB
__device__ int   g_is64;               // layout flag for edge_index

__device__ __forceinline__ float lrelu(float v) {
    return v > 0.f ? v : NEG_SLOPE * v;
}

// ---- detect whether edge_index buffer is int32 or int64 (little-endian) ----
// If int64, every odd 32-bit word is the high half of a value in [0,1e5) == 0.
__global__ void detect_idx(const int* __restrict__ w) {
    int allz = 1;
#pragma unroll
    for (int i = 0; i < 128; i++) {
        if (w[2 * i + 1] != 0) { allz = 0; break; }
    }
    g_is64 = allz;
}

// ---- edge_index -> int32 src/dst (clamped for safety) ----
__global__ void conv_idx(const int* __restrict__ w) {
    int t = blockIdx.x * blockDim.x + threadIdx.x;
    if (t >= EE) return;
    int s, d;
    if (g_is64) {
        s = w[2 * t];
        d = w[2 * (EE + t)];
    } else {
        s = w[t];
        d = w[EE + t];
    }
    // clamp: never allow OOB downstream
    s = min(max(s, 0), NN - 1);
    d = min(max(d, 0), NN - 1);
    g_src[t] = s;
    g_dst[t] = d;
}

// ---- zero out-accumulator and denominators ----
__global__ void zero_scratch() {
    int t = blockIdx.x * blockDim.x + threadIdx.x;
    if (t < NN * CC) g_out[t] = 0.f;
    if (t < NN * HH) g_denom[t] = 0.f;
}

// ---- xl = in @ Wl, xr = in @ Wr  (both 64x64, weights in smem) ----
#define NPB 32  // nodes per block
__global__ void gemm_lr(const float* __restrict__ xin, int use_gh,
                        const float* __restrict__ Wl,
                        const float* __restrict__ Wr) {
    __shared__ float sW[2][64][64];   // 32 KB
    __shared__ float sx[NPB][64];     // 8 KB
    const float* in = use_gh ? g_h : xin;

    int tx = threadIdx.x;            // 0..63 : output column
    int ty = threadIdx.y;            // 0..3
    int tid = ty * 64 + tx;

    for (int i = tid; i < 4096; i += 256) {
        sW[0][i >> 6][i & 63] = Wl[i];
        sW[1][i >> 6][i & 63] = Wr[i];
    }
    int base = blockIdx.x * NPB;
    for (int i = tid; i < NPB * 64; i += 256) {
        int n = base + (i >> 6);
        sx[i >> 6][i & 63] = (n < NN) ? in[n * 64 + (i & 63)] : 0.f;
    }
    __syncthreads();

    float accl[NPB / 4], accr[NPB / 4];
#pragma unroll
    for (int j = 0; j < NPB / 4; j++) { accl[j] = 0.f; accr[j] = 0.f; }

#pragma unroll 4
    for (int k = 0; k < 64; k++) {
        float wl = sW[0][k][tx];
        float wr = sW[1][k][tx];
#pragma unroll
        for (int j = 0; j < NPB / 4; j++) {
            float xv = sx[ty + 4 * j][k];   // warp-broadcast
            accl[j] += xv * wl;
            accr[j] += xv * wr;
        }
    }

#pragma unroll
    for (int j = 0; j < NPB / 4; j++) {
        int n = base + ty + 4 * j;
        if (n < NN) {
            g_xl[n * 64 + tx] = accl[j];
            g_xr[n * 64 + tx] = accr[j];
        }
    }
}

// ---- pass 1: logits -> exp -> denom ----
// one thread per (edge, head); 4 consecutive threads share an edge
__global__ void edge_pass1(const float* __restrict__ a) {
    int t = blockIdx.x * blockDim.x + threadIdx.x;
    if (t >= EE * HH) return;
    int e = t >> 2;
    int h = t & 3;
    int s = g_src[e];
    int d = g_dst[e];

    const float4* pl = reinterpret_cast<const float4*>(g_xl + (size_t)s * 64 + h * 16);
    const float4* pr = reinterpret_cast<const float4*>(g_xr + (size_t)d * 64 + h * 16);
    const float4* pa = reinterpret_cast<const float4*>(a + h * 16);

    float acc = 0.f;
#pragma unroll
    for (int i = 0; i < 4; i++) {
        float4 l = pl[i];
        float4 r = pr[i];
        float4 av = pa[i];
        acc += lrelu(l.x + r.x) * av.x;
        acc += lrelu(l.y + r.y) * av.y;
        acc += lrelu(l.z + r.z) * av.z;
        acc += lrelu(l.w + r.w) * av.w;
    }
    float v = __expf(acc);
    g_ex[t] = v;
    atomicAdd(g_denom + d * 4 + h, v);
}

// ---- pass 2: alpha-weighted scatter-add of xl[src] into out[dst] ----
__global__ void edge_pass2() {
    int t = blockIdx.x * blockDim.x + threadIdx.x;
    if (t >= EE * HH) return;
    int e = t >> 2;
    int h = t & 3;
    int s = g_src[e];
    int d = g_dst[e];

    float alpha = g_ex[t] / (g_denom[d * 4 + h] + 1e-16f);

    const float4* pl = reinterpret_cast<const float4*>(g_xl + (size_t)s * 64 + h * 16);
    float* po = g_out + (size_t)d * 64 + h * 16;
#pragma unroll
    for (int i = 0; i < 4; i++) {
        float4 l = pl[i];
        atomicAdd(po + 4 * i + 0, l.x * alpha);
        atomicAdd(po + 4 * i + 1, l.y * alpha);
        atomicAdd(po + 4 * i + 2, l.z * alpha);
        atomicAdd(po + 4 * i + 3, l.w * alpha);
    }
}

// ---- +bias, optional relu, route to g_h or d_out ----
__global__ void finalize(const float* __restrict__ b, float* __restrict__ dout,
                         int layer) {
    int t = blockIdx.x * blockDim.x + threadIdx.x;
    if (t >= NN * CC) return;
    float v = g_out[t] + b[t & 63];
    if (layer < 2) {
        g_h[t] = fmaxf(v, 0.f);
    } else {
        dout[t] = v;
    }
}

extern "C" void kernel_launch(void* const* d_in, const int* in_sizes, int n_in,
                              void* d_out, int out_size) {
    const float* x = (const float*)d_in[0];
    const int* ei = (const int*)d_in[1];

    detect_idx<<<1, 1>>>(ei);
    conv_idx<<<(EE + 255) / 256, 256>>>(ei);

    for (int l = 0; l < 3; l++) {
        const float* Wl = (const float*)d_in[2 + 4 * l];
        const float* Wr = (const float*)d_in[3 + 4 * l];
        const float* a  = (const float*)d_in[4 + 4 * l];
        const float* b  = (const float*)d_in[5 + 4 * l];

        gemm_lr<<<(NN + NPB - 1) / NPB, dim3(64, 4)>>>(x, l > 0 ? 1 : 0, Wl, Wr);
        zero_scratch<<<(NN * CC + 255) / 256, 256>>>();
        edge_pass1<<<(EE * HH + 255) / 256, 256>>>(a);
        edge_pass2<<<(EE * HH + 255) / 256, 256>>>();
        finalize<<<(NN * CC + 255) / 256, 256>>>(b, (float*)d_out, l);
    }
}

// round 3
// speedup vs baseline: 1.8665x; 1.8665x over previous
#include <cuda_runtime.h>

// GATv2 x3 layers. N=100000 nodes, E=1000000 edges, C=64, H=4, O=16.
//
// Pipeline per layer:
//   1. gemm_lr   : xl = in@Wl, xr = in@Wr            (smem-tiled fp32 FMA)
//   2. edge_pass1: e = a . lrelu(xl[src]+xr[dst]); ex=exp(e); denom[dst] += ex
//      (segment-max skipped: alpha invariant to shift; logits are O(1))
//   3. edge_pass2: alpha = ex/denom[dst]; out[dst] += alpha*xl[src]
//      via red.global.add.v4.f32 (4 vector reductions instead of 16 scalars)
//   4. finalize  : +bias, relu (layers 1,2) -> g_h, or -> d_out (layer 3);
//                  also resets g_out/g_denom for the NEXT layer (fused zero).

#define NN 100000
#define EE 1000000
#define CC 64
#define HH 4
#define OO 16
#define NEG_SLOPE 0.2f

// ---- scratch (device globals; no runtime allocation allowed) ----
__device__ float g_xl[NN * CC];
__device__ float g_xr[NN * CC];
__device__ float g_h[NN * CC];
__device__ float g_out[NN * CC];
__device__ float g_ex[EE * HH];
__device__ float g_denom[NN * HH];
__device__ int   g_src[EE];
__device__ int   g_dst[EE];
__device__ int   g_is64;

__device__ __forceinline__ float lrelu(float v) {
    return v > 0.f ? v : NEG_SLOPE * v;
}

__device__ __forceinline__ void red_add_v4(float* p, float x, float y, float z, float w) {
    asm volatile("red.global.add.v4.f32 [%0], {%1,%2,%3,%4};"
                 :: "l"(p), "f"(x), "f"(y), "f"(z), "f"(w) : "memory");
}

__device__ __forceinline__ void red_add_f32(float* p, float v) {
    asm volatile("red.global.add.f32 [%0], %1;" :: "l"(p), "f"(v) : "memory");
}

// ---- detect whether edge_index buffer is int32 or int64 (little-endian) ----
__global__ void detect_idx(const int* __restrict__ w) {
    int allz = 1;
#pragma unroll
    for (int i = 0; i < 128; i++) {
        if (w[2 * i + 1] != 0) { allz = 0; break; }
    }
    g_is64 = allz;
}

// ---- edge_index -> int32 src/dst (clamped) ----
__global__ void conv_idx(const int* __restrict__ w) {
    int t = blockIdx.x * blockDim.x + threadIdx.x;
    if (t >= EE) return;
    int s, d;
    if (g_is64) {
        s = w[2 * t];
        d = w[2 * (EE + t)];
    } else {
        s = w[t];
        d = w[EE + t];
    }
    s = min(max(s, 0), NN - 1);
    d = min(max(d, 0), NN - 1);
    g_src[t] = s;
    g_dst[t] = d;
}

// ---- one-time zero before layer 0 (afterwards finalize resets) ----
__global__ void zero_scratch() {
    int t = blockIdx.x * blockDim.x + threadIdx.x;
    if (t < NN * CC) g_out[t] = 0.f;
    if (t < NN * HH) g_denom[t] = 0.f;
}

// ---- xl = in @ Wl, xr = in @ Wr  (both 64x64, weights in smem) ----
#define NPB 32
__global__ void gemm_lr(const float* __restrict__ xin, int use_gh,
                        const float* __restrict__ Wl,
                        const float* __restrict__ Wr) {
    __shared__ float sW[2][64][64];
    __shared__ float sx[NPB][64];
    const float* in = use_gh ? g_h : xin;

    int tx = threadIdx.x;            // 0..63 : output column
    int ty = threadIdx.y;            // 0..3
    int tid = ty * 64 + tx;

    for (int i = tid; i < 4096; i += 256) {
        sW[0][i >> 6][i & 63] = Wl[i];
        sW[1][i >> 6][i & 63] = Wr[i];
    }
    int base = blockIdx.x * NPB;
    for (int i = tid; i < NPB * 64; i += 256) {
        int n = base + (i >> 6);
        sx[i >> 6][i & 63] = (n < NN) ? in[n * 64 + (i & 63)] : 0.f;
    }
    __syncthreads();

    float accl[NPB / 4], accr[NPB / 4];
#pragma unroll
    for (int j = 0; j < NPB / 4; j++) { accl[j] = 0.f; accr[j] = 0.f; }

#pragma unroll 4
    for (int k = 0; k < 64; k++) {
        float wl = sW[0][k][tx];
        float wr = sW[1][k][tx];
#pragma unroll
        for (int j = 0; j < NPB / 4; j++) {
            float xv = sx[ty + 4 * j][k];
            accl[j] += xv * wl;
            accr[j] += xv * wr;
        }
    }

#pragma unroll
    for (int j = 0; j < NPB / 4; j++) {
        int n = base + ty + 4 * j;
        if (n < NN) {
            g_xl[n * 64 + tx] = accl[j];
            g_xr[n * 64 + tx] = accr[j];
        }
    }
}

// ---- pass 1: logits -> exp -> denom ----
__global__ void edge_pass1(const float* __restrict__ a) {
    int t = blockIdx.x * blockDim.x + threadIdx.x;
    if (t >= EE * HH) return;
    int e = t >> 2;
    int h = t & 3;
    int s = g_src[e];
    int d = g_dst[e];

    const float4* pl = reinterpret_cast<const float4*>(g_xl + (size_t)s * 64 + h * 16);
    const float4* pr = reinterpret_cast<const float4*>(g_xr + (size_t)d * 64 + h * 16);
    const float4* pa = reinterpret_cast<const float4*>(a + h * 16);

    float acc = 0.f;
#pragma unroll
    for (int i = 0; i < 4; i++) {
        float4 l = pl[i];
        float4 r = pr[i];
        float4 av = pa[i];
        acc += lrelu(l.x + r.x) * av.x;
        acc += lrelu(l.y + r.y) * av.y;
        acc += lrelu(l.z + r.z) * av.z;
        acc += lrelu(l.w + r.w) * av.w;
    }
    float v = __expf(acc);
    g_ex[t] = v;
    red_add_f32(g_denom + d * 4 + h, v);
}

// ---- pass 2: alpha-weighted scatter-add of xl[src] into out[dst] ----
__global__ void edge_pass2() {
    int t = blockIdx.x * blockDim.x + threadIdx.x;
    if (t >= EE * HH) return;
    int e = t >> 2;
    int h = t & 3;
    int s = g_src[e];
    int d = g_dst[e];

    float alpha = g_ex[t] / (g_denom[d * 4 + h] + 1e-16f);

    const float4* pl = reinterpret_cast<const float4*>(g_xl + (size_t)s * 64 + h * 16);
    float* po = g_out + (size_t)d * 64 + h * 16;
#pragma unroll
    for (int i = 0; i < 4; i++) {
        float4 l = pl[i];
        red_add_v4(po + 4 * i, l.x * alpha, l.y * alpha, l.z * alpha, l.w * alpha);
    }
}

// ---- +bias, optional relu, route; reset scratch for next layer ----
__global__ void finalize(const float* __restrict__ b, float* __restrict__ dout,
                         int layer) {
    int t = blockIdx.x * blockDim.x + threadIdx.x;
    if (t >= NN * CC) return;
    float v = g_out[t] + b[t & 63];
    if (layer < 2) {
        g_h[t] = fmaxf(v, 0.f);
        g_out[t] = 0.f;                      // reset accumulator for next layer
        if (t < NN * HH) g_denom[t] = 0.f;   // reset denom for next layer
    } else {
        dout[t] = v;
    }
}

extern "C" void kernel_launch(void* const* d_in, const int* in_sizes, int n_in,
                              void* d_out, int out_size) {
    const float* x = (const float*)d_in[0];
    const int* ei = (const int*)d_in[1];

    detect_idx<<<1, 1>>>(ei);
    conv_idx<<<(EE + 255) / 256, 256>>>(ei);
    zero_scratch<<<(NN * CC + 255) / 256, 256>>>();

    for (int l = 0; l < 3; l++) {
        const float* Wl = (const float*)d_in[2 + 4 * l];
        const float* Wr = (const float*)d_in[3 + 4 * l];
        const float* a  = (const float*)d_in[4 + 4 * l];
        const float* b  = (const float*)d_in[5 + 4 * l];

        gemm_lr<<<(NN + NPB - 1) / NPB, dim3(64, 4)>>>(x, l > 0 ? 1 : 0, Wl, Wr);
        edge_pass1<<<(EE * HH + 255) / 256, 256>>>(a);
        edge_pass2<<<(EE * HH + 255) / 256, 256>>>();
        finalize<<<(NN * CC + 255) / 256, 256>>>(b, (float*)d_out, l);
    }
}

// round 4
// speedup vs baseline: 3.5001x; 1.8752x over previous
#include <cuda_runtime.h>

// GATv2 x3 layers. N=100000 nodes, E=1000000 edges, C=64, H=4, O=16.
//
// Per launch: build CSR by dst (hist -> scan -> scatter), then per layer:
//   1. gemm_lr  : xl = in@Wl, xr = in@Wr  (register-tiled fp32)
//   2. node_agg : one warp per dst node; fused logits+softmax+aggregate+bias.
//      out[d] = (sum_e ex_e * xl[src_e]) / (sum_e ex_e + 1e-16) + b
//      -> no atomics, xl gathered once, ex never stored.
//      (segment-max skipped: alpha invariant to shift; logits are O(1))

#define NN 100000
#define EE 1000000
#define CC 64
#define HH 4
#define NEG_SLOPE 0.2f
#define NBLK ((NN + 255) / 256)   // 391

// ---- scratch (device globals; no runtime allocation allowed) ----
__device__ float g_xl[NN * CC];
__device__ float g_xr[NN * CC];
__device__ float g_h[NN * CC];
__device__ int   g_src[EE];
__device__ int   g_dst[EE];
__device__ int   g_srcs[EE];       // CSR: src sorted by dst
__device__ int   g_cnt[NN];
__device__ int   g_off[NN + 1];
__device__ int   g_cur[NN];
__device__ int   g_bsum[NBLK + 1];
__device__ int   g_bbase[NBLK + 1];
__device__ int   g_is64;

__device__ __forceinline__ float lrelu(float v) {
    return v > 0.f ? v : NEG_SLOPE * v;
}

// ---- detect int32 vs int64 edge_index (little-endian) ----
__global__ void detect_idx(const int* __restrict__ w) {
    int allz = 1;
#pragma unroll
    for (int i = 0; i < 128; i++) {
        if (w[2 * i + 1] != 0) { allz = 0; break; }
    }
    g_is64 = allz;
}

__global__ void zero_cnt() {
    int t = blockIdx.x * blockDim.x + threadIdx.x;
    if (t < NN) g_cnt[t] = 0;
}

// ---- edge_index -> int32 src/dst (clamped) + dst histogram ----
__global__ void conv_idx(const int* __restrict__ w) {
    int t = blockIdx.x * blockDim.x + threadIdx.x;
    if (t >= EE) return;
    int s, d;
    if (g_is64) {
        s = w[2 * t];
        d = w[2 * (EE + t)];
    } else {
        s = w[t];
        d = w[EE + t];
    }
    s = min(max(s, 0), NN - 1);
    d = min(max(d, 0), NN - 1);
    g_src[t] = s;
    g_dst[t] = d;
    atomicAdd(&g_cnt[d], 1);
}

// ---- 3-kernel exclusive scan of g_cnt -> g_off / g_cur ----
__global__ void scan_part() {
    __shared__ int sh[256];
    int t = threadIdx.x;
    int i = blockIdx.x * 256 + t;
    int v = (i < NN) ? g_cnt[i] : 0;
    sh[t] = v;
    __syncthreads();
    for (int d = 128; d > 0; d >>= 1) {
        if (t < d) sh[t] += sh[t + d];
        __syncthreads();
    }
    if (t == 0) g_bsum[blockIdx.x] = sh[0];
}

__global__ void scan_top() {   // 1 block, 512 threads (NBLK=391)
    __shared__ int sh[512];
    int t = threadIdx.x;
    int v = (t < NBLK) ? g_bsum[t] : 0;
    sh[t] = v;
    __syncthreads();
    for (int d = 1; d < 512; d <<= 1) {
        int tmp = (t >= d) ? sh[t - d] : 0;
        __syncthreads();
        sh[t] += tmp;
        __syncthreads();
    }
    if (t < NBLK) g_bbase[t] = sh[t] - v;   // exclusive
}

__global__ void scan_apply() {
    __shared__ int sh[256];
    int t = threadIdx.x;
    int i = blockIdx.x * 256 + t;
    int v = (i < NN) ? g_cnt[i] : 0;
    sh[t] = v;
    __syncthreads();
    for (int d = 1; d < 256; d <<= 1) {
        int tmp = (t >= d) ? sh[t - d] : 0;
        __syncthreads();
        sh[t] += tmp;
        __syncthreads();
    }
    int excl = sh[t] - v + g_bbase[blockIdx.x];
    if (i < NN) {
        g_off[i] = excl;
        g_cur[i] = excl;
    }
    if (i == 0) g_off[NN] = EE;
}

__global__ void scatter_csr() {
    int e = blockIdx.x * blockDim.x + threadIdx.x;
    if (e >= EE) return;
    int d = g_dst[e];
    int pos = atomicAdd(&g_cur[d], 1);
    g_srcs[pos] = g_src[e];
}

// ---- xl = in @ Wl, xr = in @ Wr : 64 nodes x 128 cols per block ----
__global__ void __launch_bounds__(256) gemm_lr(
        const float* __restrict__ xin, int use_gh,
        const float* __restrict__ Wl, const float* __restrict__ Wr) {
    __shared__ float sW[64][128];   // [k][col]; col<64 -> Wl, else Wr  (32 KB)
    __shared__ float sx[64][64];    // [node][k]                        (16 KB)
    const float* in = use_gh ? g_h : xin;

    int tid = threadIdx.x;
    int lane = tid & 31;            // col group: 4*lane of 128
    int wrp = tid >> 5;             // node group: wrp + 8*j

    for (int i = tid; i < 4096; i += 256) {
        int k = i >> 6, c = i & 63;
        sW[k][c] = Wl[i];
        sW[k][64 + c] = Wr[i];
    }
    int base = blockIdx.x * 64;
    for (int i = tid; i < 1024; i += 256) {        // 64 nodes x 16 float4
        int n = i >> 4, q = i & 15;
        int node = base + n;
        float4 v = make_float4(0.f, 0.f, 0.f, 0.f);
        if (node < NN) v = ((const float4*)(in + (size_t)node * 64))[q];
        ((float4*)&sx[n][0])[q] = v;
    }
    __syncthreads();

    float acc[8][4];
#pragma unroll
    for (int j = 0; j < 8; j++) {
        acc[j][0] = 0.f; acc[j][1] = 0.f; acc[j][2] = 0.f; acc[j][3] = 0.f;
    }

#pragma unroll 8
    for (int k = 0; k < 64; k++) {
        float4 w = ((const float4*)&sW[k][0])[lane];
#pragma unroll
        for (int j = 0; j < 8; j++) {
            float xv = sx[wrp + 8 * j][k];     // warp-broadcast
            acc[j][0] += xv * w.x;
            acc[j][1] += xv * w.y;
            acc[j][2] += xv * w.z;
            acc[j][3] += xv * w.w;
        }
    }

    int colg = lane * 4;
#pragma unroll
    for (int j = 0; j < 8; j++) {
        int node = base + wrp + 8 * j;
        if (node < NN) {
            float4 v = make_float4(acc[j][0], acc[j][1], acc[j][2], acc[j][3]);
            if (colg < 64)
                *(float4*)(g_xl + (size_t)node * 64 + colg) = v;
            else
                *(float4*)(g_xr + (size_t)node * 64 + colg - 64) = v;
        }
    }
}

// ---- fused edge phase: one warp per dst node ----
// lane owns channels c0=2*lane, c0+1 (head h = lane/8 covers lanes 8h..8h+7)
__global__ void node_agg(const float* __restrict__ a, const float* __restrict__ b,
                         float* __restrict__ dout, int layer) {
    int gw = (blockIdx.x * blockDim.x + threadIdx.x) >> 5;
    int lane = threadIdx.x & 31;
    if (gw >= NN) return;
    int d = gw;
    int c0 = lane * 2;

    float2 xr2 = *(const float2*)(g_xr + (size_t)d * 64 + c0);
    float2 a2  = *(const float2*)(a + c0);

    int beg = g_off[d], end = g_off[d + 1];
    float denom = 0.f, acc0 = 0.f, acc1 = 0.f;

    for (int base = beg; base < end; base += 32) {
        int n = min(32, end - base);
        int my_s = (base + lane < end) ? g_srcs[base + lane] : 0;

        // software pipeline: prefetch next edge's xl
        int s = __shfl_sync(0xffffffffu, my_s, 0);
        float2 xl2 = *(const float2*)(g_xl + (size_t)s * 64 + c0);

        for (int j = 0; j < n; j++) {
            float2 cur = xl2;
            if (j + 1 < n) {
                int sn = __shfl_sync(0xffffffffu, my_s, j + 1);
                xl2 = *(const float2*)(g_xl + (size_t)sn * 64 + c0);
            }
            float p = lrelu(cur.x + xr2.x) * a2.x + lrelu(cur.y + xr2.y) * a2.y;
            p += __shfl_xor_sync(0xffffffffu, p, 1);
            p += __shfl_xor_sync(0xffffffffu, p, 2);
            p += __shfl_xor_sync(0xffffffffu, p, 4);
            float ex = __expf(p);
            denom += ex;
            acc0 += ex * cur.x;
            acc1 += ex * cur.y;
        }
    }

    float inv = 1.f / (denom + 1e-16f);
    float v0 = acc0 * inv + b[c0];
    float v1 = acc1 * inv + b[c0 + 1];
    size_t o = (size_t)d * 64 + c0;
    if (layer < 2) {
        g_h[o]     = fmaxf(v0, 0.f);
        g_h[o + 1] = fmaxf(v1, 0.f);
    } else {
        dout[o]     = v0;
        dout[o + 1] = v1;
    }
}

extern "C" void kernel_launch(void* const* d_in, const int* in_sizes, int n_in,
                              void* d_out, int out_size) {
    const float* x = (const float*)d_in[0];
    const int* ei = (const int*)d_in[1];

    detect_idx<<<1, 1>>>(ei);
    zero_cnt<<<NBLK, 256>>>();
    conv_idx<<<(EE + 255) / 256, 256>>>(ei);
    scan_part<<<NBLK, 256>>>();
    scan_top<<<1, 512>>>();
    scan_apply<<<NBLK, 256>>>();
    scatter_csr<<<(EE + 255) / 256, 256>>>();

    for (int l = 0; l < 3; l++) {
        const float* Wl = (const float*)d_in[2 + 4 * l];
        const float* Wr = (const float*)d_in[3 + 4 * l];
        const float* a  = (const float*)d_in[4 + 4 * l];
        const float* b  = (const float*)d_in[5 + 4 * l];

        gemm_lr<<<(NN + 63) / 64, 256>>>(x, l > 0 ? 1 : 0, Wl, Wr);
        node_agg<<<(NN * 32 + 255) / 256, 256>>>(a, b, (float*)d_out, l);
    }
}

// round 5
// speedup vs baseline: 3.7090x; 1.0597x over previous
#include <cuda_runtime.h>

// GATv2 x3 layers. N=100000 nodes, E=1000000 edges, C=64, H=4, O=16.
//
// Per launch: build CSR by dst (hist -> scan -> scatter, reading edge_index
// directly), then per layer:
//   1. gemm_lr  : xl = in@Wl, xr = in@Wr  (register-tiled fp32)
//   2. node_agg : one warp per dst node; TWO edges in flight per iteration
//      (lane = 16*edge_half + channel_quad). Fused logits+softmax+agg+bias,
//      no atomics, xl gathered once, ex never materialized.
//      (segment-max skipped: alpha invariant to shift; logits are O(1))

#define NN 100000
#define EE 1000000
#define CC 64
#define HH 4
#define NEG_SLOPE 0.2f
#define NBLK ((NN + 255) / 256)   // 391
#define FULL 0xffffffffu

// ---- scratch (device globals; no runtime allocation allowed) ----
__device__ float g_xl[NN * CC];
__device__ float g_xr[NN * CC];
__device__ float g_h[NN * CC];
__device__ int   g_srcs[EE];       // CSR: src sorted by dst
__device__ int   g_cnt[NN];
__device__ int   g_off[NN + 1];
__device__ int   g_cur[NN];
__device__ int   g_bsum[NBLK + 1];
__device__ int   g_bbase[NBLK + 1];
__device__ int   g_is64;

__device__ __forceinline__ float lrelu(float v) {
    return v > 0.f ? v : NEG_SLOPE * v;
}

// ---- detect int32 vs int64 edge_index (little-endian) ----
__global__ void detect_idx(const int* __restrict__ w) {
    int allz = 1;
#pragma unroll
    for (int i = 0; i < 128; i++) {
        if (w[2 * i + 1] != 0) { allz = 0; break; }
    }
    g_is64 = allz;
}

__global__ void zero_cnt() {
    int t = blockIdx.x * blockDim.x + threadIdx.x;
    if (t < NN) g_cnt[t] = 0;
}

// ---- dst histogram straight off edge_index ----
__global__ void hist_dst(const int* __restrict__ w) {
    int t = blockIdx.x * blockDim.x + threadIdx.x;
    if (t >= EE) return;
    int d = g_is64 ? w[2 * (EE + t)] : w[EE + t];
    d = min(max(d, 0), NN - 1);
    atomicAdd(&g_cnt[d], 1);
}

// ---- 3-kernel exclusive scan of g_cnt -> g_off / g_cur ----
__global__ void scan_part() {
    __shared__ int sh[256];
    int t = threadIdx.x;
    int i = blockIdx.x * 256 + t;
    int v = (i < NN) ? g_cnt[i] : 0;
    sh[t] = v;
    __syncthreads();
    for (int d = 128; d > 0; d >>= 1) {
        if (t < d) sh[t] += sh[t + d];
        __syncthreads();
    }
    if (t == 0) g_bsum[blockIdx.x] = sh[0];
}

__global__ void scan_top() {   // 1 block, 512 threads (NBLK=391)
    __shared__ int sh[512];
    int t = threadIdx.x;
    int v = (t < NBLK) ? g_bsum[t] : 0;
    sh[t] = v;
    __syncthreads();
    for (int d = 1; d < 512; d <<= 1) {
        int tmp = (t >= d) ? sh[t - d] : 0;
        __syncthreads();
        sh[t] += tmp;
        __syncthreads();
    }
    if (t < NBLK) g_bbase[t] = sh[t] - v;   // exclusive
}

__global__ void scan_apply() {
    __shared__ int sh[256];
    int t = threadIdx.x;
    int i = blockIdx.x * 256 + t;
    int v = (i < NN) ? g_cnt[i] : 0;
    sh[t] = v;
    __syncthreads();
    for (int d = 1; d < 256; d <<= 1) {
        int tmp = (t >= d) ? sh[t - d] : 0;
        __syncthreads();
        sh[t] += tmp;
        __syncthreads();
    }
    int excl = sh[t] - v + g_bbase[blockIdx.x];
    if (i < NN) {
        g_off[i] = excl;
        g_cur[i] = excl;
    }
    if (i == 0) g_off[NN] = EE;
}

__global__ void scatter_csr(const int* __restrict__ w) {
    int t = blockIdx.x * blockDim.x + threadIdx.x;
    if (t >= EE) return;
    int s, d;
    if (g_is64) {
        s = w[2 * t];
        d = w[2 * (EE + t)];
    } else {
        s = w[t];
        d = w[EE + t];
    }
    s = min(max(s, 0), NN - 1);
    d = min(max(d, 0), NN - 1);
    int pos = atomicAdd(&g_cur[d], 1);
    g_srcs[pos] = s;
}

// ---- xl = in @ Wl, xr = in @ Wr : 64 nodes x 128 cols per block ----
__global__ void __launch_bounds__(256) gemm_lr(
        const float* __restrict__ xin, int use_gh,
        const float* __restrict__ Wl, const float* __restrict__ Wr) {
    __shared__ float sW[64][128];   // [k][col]; col<64 -> Wl, else Wr
    __shared__ float sx[64][64];    // [node][k]
    const float* in = use_gh ? g_h : xin;

    int tid = threadIdx.x;
    int lane = tid & 31;            // col group: 4*lane of 128
    int wrp = tid >> 5;             // node group: wrp + 8*j

    for (int i = tid; i < 4096; i += 256) {
        int k = i >> 6, c = i & 63;
        sW[k][c] = Wl[i];
        sW[k][64 + c] = Wr[i];
    }
    int base = blockIdx.x * 64;
    for (int i = tid; i < 1024; i += 256) {        // 64 nodes x 16 float4
        int n = i >> 4, q = i & 15;
        int node = base + n;
        float4 v = make_float4(0.f, 0.f, 0.f, 0.f);
        if (node < NN) v = ((const float4*)(in + (size_t)node * 64))[q];
        ((float4*)&sx[n][0])[q] = v;
    }
    __syncthreads();

    float acc[8][4];
#pragma unroll
    for (int j = 0; j < 8; j++) {
        acc[j][0] = 0.f; acc[j][1] = 0.f; acc[j][2] = 0.f; acc[j][3] = 0.f;
    }

#pragma unroll 8
    for (int k = 0; k < 64; k++) {
        float4 w = ((const float4*)&sW[k][0])[lane];
#pragma unroll
        for (int j = 0; j < 8; j++) {
            float xv = sx[wrp + 8 * j][k];     // warp-broadcast
            acc[j][0] += xv * w.x;
            acc[j][1] += xv * w.y;
            acc[j][2] += xv * w.z;
            acc[j][3] += xv * w.w;
        }
    }

    int colg = lane * 4;
#pragma unroll
    for (int j = 0; j < 8; j++) {
        int node = base + wrp + 8 * j;
        if (node < NN) {
            float4 v = make_float4(acc[j][0], acc[j][1], acc[j][2], acc[j][3]);
            if (colg < 64)
                *(float4*)(g_xl + (size_t)node * 64 + colg) = v;
            else
                *(float4*)(g_xr + (size_t)node * 64 + colg - 64) = v;
        }
    }
}

// ---- fused edge phase: one warp per dst node, 2 edges per iteration ----
// lane = 16*half + q : half = which edge of the pair, q*4 = channel quad.
// head h = q>>2; logit reduction = shfl_xor 1,2 within the 4-lane head group.
__global__ void node_agg(const float* __restrict__ a, const float* __restrict__ b,
                         float* __restrict__ dout, int layer) {
    int gw = (blockIdx.x * blockDim.x + threadIdx.x) >> 5;
    int lane = threadIdx.x & 31;
    if (gw >= NN) return;
    int d = gw;
    int half = lane >> 4;
    int q = lane & 15;
    int c0 = q * 4;

    float4 xr4 = *(const float4*)(g_xr + (size_t)d * 64 + c0);
    float4 a4  = *(const float4*)(a + c0);

    int beg = g_off[d], end = g_off[d + 1];
    float denom = 0.f;
    float ac0 = 0.f, ac1 = 0.f, ac2 = 0.f, ac3 = 0.f;

    for (int base = beg; base < end; base += 32) {
        int n = min(32, end - base);
        int my_s = (base + lane < end) ? g_srcs[base + lane] : 0;
        int npair = (n + 1) >> 1;

        int s = __shfl_sync(FULL, my_s, half);     // edge {0,1}
        float4 xl = *(const float4*)(g_xl + (size_t)s * 64 + c0);

        for (int jp = 0; jp < npair; jp++) {
            float4 cur = xl;
            int ecur = 2 * jp + half;
            if (jp + 1 < npair) {
                int sn = __shfl_sync(FULL, my_s, 2 * (jp + 1) + half);
                xl = *(const float4*)(g_xl + (size_t)sn * 64 + c0);
            }
            float p = lrelu(cur.x + xr4.x) * a4.x
                    + lrelu(cur.y + xr4.y) * a4.y
                    + lrelu(cur.z + xr4.z) * a4.z
                    + lrelu(cur.w + xr4.w) * a4.w;
            p += __shfl_xor_sync(FULL, p, 1);
            p += __shfl_xor_sync(FULL, p, 2);
            float ex = __expf(p);
            if (ecur >= n) ex = 0.f;               // odd tail: upper half idle
            denom += ex;
            ac0 += ex * cur.x;
            ac1 += ex * cur.y;
            ac2 += ex * cur.z;
            ac3 += ex * cur.w;
        }
    }

    // combine the two edge-halves
    denom += __shfl_xor_sync(FULL, denom, 16);
    ac0   += __shfl_xor_sync(FULL, ac0, 16);
    ac1   += __shfl_xor_sync(FULL, ac1, 16);
    ac2   += __shfl_xor_sync(FULL, ac2, 16);
    ac3   += __shfl_xor_sync(FULL, ac3, 16);

    if (half == 0) {
        float inv = 1.f / (denom + 1e-16f);
        float4 b4 = *(const float4*)(b + c0);
        float4 v = make_float4(ac0 * inv + b4.x, ac1 * inv + b4.y,
                               ac2 * inv + b4.z, ac3 * inv + b4.w);
        if (layer < 2) {
            v.x = fmaxf(v.x, 0.f); v.y = fmaxf(v.y, 0.f);
            v.z = fmaxf(v.z, 0.f); v.w = fmaxf(v.w, 0.f);
            *(float4*)(g_h + (size_t)d * 64 + c0) = v;
        } else {
            *(float4*)(dout + (size_t)d * 64 + c0) = v;
        }
    }
}

extern "C" void kernel_launch(void* const* d_in, const int* in_sizes, int n_in,
                              void* d_out, int out_size) {
    const float* x = (const float*)d_in[0];
    const int* ei = (const int*)d_in[1];

    detect_idx<<<1, 1>>>(ei);
    zero_cnt<<<NBLK, 256>>>();
    hist_dst<<<(EE + 255) / 256, 256>>>(ei);
    scan_part<<<NBLK, 256>>>();
    scan_top<<<1, 512>>>();
    scan_apply<<<NBLK, 256>>>();
    scatter_csr<<<(EE + 255) / 256, 256>>>(ei);

    for (int l = 0; l < 3; l++) {
        const float* Wl = (const float*)d_in[2 + 4 * l];
        const float* Wr = (const float*)d_in[3 + 4 * l];
        const float* a  = (const float*)d_in[4 + 4 * l];
        const float* b  = (const float*)d_in[5 + 4 * l];

        gemm_lr<<<(NN + 63) / 64, 256>>>(x, l > 0 ? 1 : 0, Wl, Wr);
        node_agg<<<(NN * 32 + 255) / 256, 256>>>(a, b, (float*)d_out, l);
    }
}